// round 1
// baseline (speedup 1.0000x reference)
#include <cuda_runtime.h>
#include <cstdint>

// Problem constants (fixed shapes for this problem instance)
#define B_ 32
#define T_ 10
#define P_ 25
#define H_ 100
#define W_ 100

// Total output elems: B*T*H*W*P = 80,000,000 floats (divisible by 4)
#define OUT_ELEMS (B_ * T_ * H_ * W_ * P_)
#define OUT_VEC4  (OUT_ELEMS / 4)

// ---------------------------------------------------------------------------
// Kernel 1: zero-fill the 320MB output with 16B vector stores.
// Pure HBM-store-bound; grid sized so each thread does exactly one float4.
// ---------------------------------------------------------------------------
__global__ void zero_fill_kernel(float4* __restrict__ out) {
    size_t i = (size_t)blockIdx.x * blockDim.x + threadIdx.x;
    if (i < OUT_VEC4) {
        out[i] = make_float4(0.f, 0.f, 0.f, 0.f);
    }
}

// ---------------------------------------------------------------------------
// Kernel 2: scatter 1.0f for each in-bounds point.
// One thread per (b, t, p). Each point owns a distinct innermost-p slot, so
// writes never collide -> plain store == scatter-max semantics.
// C truncating float->int cast matches jnp .astype(int32).
// ---------------------------------------------------------------------------
__global__ void scatter_points_kernel(const float* __restrict__ x,
                                      const float* __restrict__ resolution,
                                      const float* __restrict__ origin,
                                      float* __restrict__ out) {
    int i = blockIdx.x * blockDim.x + threadIdx.x;  // 0 .. B*T*P-1
    if (i >= B_ * T_ * P_) return;

    int p  = i % P_;
    int bt = i / P_;          // b*T + t

    // x layout: [B, T, 2P]; point p is (x, y) at (2p, 2p+1)
    const float* xp = x + (size_t)bt * (2 * P_) + 2 * p;
    float px = xp[0];
    float py = xp[1];

    // resolution/origin layout: [B, T, 2]
    float res0 = resolution[2 * bt + 0];
    float res1 = resolution[2 * bt + 1];
    float org0 = origin[2 * bt + 0];
    float org1 = origin[2 * bt + 1];

    int row = (int)(py / res0 + org0);  // truncating cast, same as astype(int32)
    int col = (int)(px / res1 + org1);

    if (row >= 0 && row < H_ && col >= 0 && col < W_) {
        size_t idx = ((((size_t)bt * H_ + row) * W_) + col) * P_ + p;
        out[idx] = 1.0f;
    }
}

extern "C" void kernel_launch(void* const* d_in, const int* in_sizes, int n_in,
                              void* d_out, int out_size) {
    const float* x          = (const float*)d_in[0];
    const float* resolution = (const float*)d_in[1];
    const float* origin     = (const float*)d_in[2];
    float* out = (float*)d_out;

    // 1) zero-fill 320MB of output
    {
        const int threads = 256;
        const int blocks  = (OUT_VEC4 + threads - 1) / threads;  // 78125
        zero_fill_kernel<<<blocks, threads>>>((float4*)out);
    }

    // 2) scatter 8000 points (ordered after fill on the same stream)
    {
        const int total   = B_ * T_ * P_;  // 8000
        const int threads = 256;
        const int blocks  = (total + threads - 1) / threads;  // 32
        scatter_points_kernel<<<blocks, threads>>>(x, resolution, origin, out);
    }
}